// round 1
// baseline (speedup 1.0000x reference)
#include <cuda_runtime.h>
#include <cuda_bf16.h>

#define BB 4
#define CN 256
#define NN 4096
#define CR 32
#define OTOT 320   // 32 q + 32 k + 256 v
#define BN_TOT 16384.0f

// ---------------- scratch (device globals; no allocations allowed) ----------------
__device__ float g_mx[CN];
__device__ float g_G[CN * CN];          // Gram sums (atomic accum)
__device__ float g_WfT[CN * OTOT];      // folded weights, transposed [c][o]
__device__ float g_Bf[OTOT];            // folded bias
__device__ float g_Q[BB * NN * CR];     // [b][n][32]
__device__ float g_K[BB * NN * CR];     // [b][n][32]
__device__ float g_V[BB * NN * CN];     // [b][n][256]

// ---------------- zero Gram accumulator ----------------
__global__ void zero_kernel() {
    int i = blockIdx.x * blockDim.x + threadIdx.x;   // 256*256 = 65536
    g_G[i] = 0.0f;
}

// ---------------- per-channel mean of x over (B,N) ----------------
__global__ void mean_kernel(const float* __restrict__ x) {
    int c = blockIdx.x;
    int tid = threadIdx.x;
    float s = 0.0f;
    #pragma unroll 4
    for (int i = 0; i < 64; ++i) {
        int k = tid + i * 256;                 // 0..16383 over (b,n)
        int off = (k >> 12) * (CN * NN) + (k & 4095);
        s += x[off + c * NN];
    }
    __shared__ float red[256];
    red[tid] = s;
    __syncthreads();
    for (int st = 128; st > 0; st >>= 1) {
        if (tid < st) red[tid] += red[tid + st];
        __syncthreads();
    }
    if (tid == 0) g_mx[c] = red[0] * (1.0f / BN_TOT);
}

// ---------------- Gram: G[c,c'] = sum_{b,n} x[b,c,n] x[b,c',n] ----------------
// grid (8,8,16): 32x32 tile, K split 16 ways (1024 k each), atomic accumulate.
__global__ void gram_kernel(const float* __restrict__ x) {
    __shared__ float As[64][33];
    __shared__ float Bs[64][33];
    int c0 = blockIdx.x * 32, c1 = blockIdx.y * 32;
    int kbase = blockIdx.z * 1024;
    int tid = threadIdx.x;
    int ty = tid >> 4, tx = tid & 15;
    float acc00 = 0, acc01 = 0, acc10 = 0, acc11 = 0;
    for (int it = 0; it < 16; ++it) {
        int k0 = kbase + it * 64;
        #pragma unroll
        for (int r = 0; r < 8; ++r) {
            int idx = tid + r * 256;           // 0..2047
            int kk = idx & 63, ci = idx >> 6;  // ci 0..31
            int k = k0 + kk;
            int off = (k >> 12) * (CN * NN) + (k & 4095);
            As[kk][ci] = x[off + (c0 + ci) * NN];
            Bs[kk][ci] = x[off + (c1 + ci) * NN];
        }
        __syncthreads();
        #pragma unroll
        for (int kk = 0; kk < 64; ++kk) {
            float a0 = As[kk][2 * ty], a1 = As[kk][2 * ty + 1];
            float b0 = Bs[kk][2 * tx], b1 = Bs[kk][2 * tx + 1];
            acc00 += a0 * b0; acc01 += a0 * b1;
            acc10 += a1 * b0; acc11 += a1 * b1;
        }
        __syncthreads();
    }
    atomicAdd(&g_G[(c0 + 2 * ty    ) * CN + c1 + 2 * tx    ], acc00);
    atomicAdd(&g_G[(c0 + 2 * ty    ) * CN + c1 + 2 * tx + 1], acc01);
    atomicAdd(&g_G[(c0 + 2 * ty + 1) * CN + c1 + 2 * tx    ], acc10);
    atomicAdd(&g_G[(c0 + 2 * ty + 1) * CN + c1 + 2 * tx + 1], acc11);
}

// ---------------- fold BN into affine conv: Wf = g*rs*w, Bf = b - g*rs*mean ----------------
// one block per output channel o (320 blocks, 256 threads)
__global__ void fold_kernel(const float* __restrict__ w1, const float* __restrict__ w2,
                            const float* __restrict__ w3,
                            const float* __restrict__ g1, const float* __restrict__ b1,
                            const float* __restrict__ g2, const float* __restrict__ b2,
                            const float* __restrict__ g3, const float* __restrict__ b3) {
    int o = blockIdx.x;
    int tid = threadIdx.x;
    const float* w; float gg, bb;
    if (o < 32)       { w = w1 + o * CN;        gg = g1[o];      bb = b1[o]; }
    else if (o < 64)  { w = w2 + (o - 32) * CN; gg = g2[o - 32]; bb = b2[o - 32]; }
    else              { w = w3 + (o - 64) * CN; gg = g3[o - 64]; bb = b3[o - 64]; }

    __shared__ float ws[256];
    __shared__ float redE[256];
    __shared__ float redM[256];
    __shared__ float sc_sh;
    ws[tid] = w[tid];
    __syncthreads();
    // row of G (symmetric): use column-major access for coalescing
    float acc = 0.0f;
    #pragma unroll 4
    for (int c = 0; c < CN; ++c) acc += g_G[c * CN + tid] * ws[c];
    redE[tid] = acc * ws[tid];
    redM[tid] = ws[tid] * g_mx[tid];
    __syncthreads();
    for (int st = 128; st > 0; st >>= 1) {
        if (tid < st) { redE[tid] += redE[tid + st]; redM[tid] += redM[tid + st]; }
        __syncthreads();
    }
    if (tid == 0) {
        float m = redM[0];
        float E = redE[0] * (1.0f / BN_TOT);
        float var = E - m * m;
        float rs = rsqrtf(var + 1e-5f);
        float sc = gg * rs;
        sc_sh = sc;
        g_Bf[o] = bb - sc * m;
    }
    __syncthreads();
    g_WfT[tid * OTOT + o] = sc_sh * ws[tid];
}

// ---------------- fused conv: Z[o,n] = relu(Wf[o,:]·x[b,:,n] + Bf[o]) ----------------
// grid (5, 64, 4), block 256 (16x16, each thread 4x4). Writes Q/K/V transposed.
__global__ void qkd_kernel(const float* __restrict__ x) {
    __shared__ float Ws[16][64];
    __shared__ float Xs[16][64];
    int o0 = blockIdx.x * 64, n0 = blockIdx.y * 64, b = blockIdx.z;
    int tid = threadIdx.x;
    int ty = tid >> 4, tx = tid & 15;
    float acc[4][4] = {};
    const float* xb = x + (size_t)b * CN * NN;
    for (int k0 = 0; k0 < CN; k0 += 16) {
        #pragma unroll
        for (int r = 0; r < 4; ++r) {
            int idx = tid + r * 256;            // 0..1023
            int i = idx & 63, kk = idx >> 6;
            Ws[kk][i] = g_WfT[(k0 + kk) * OTOT + o0 + i];
            Xs[kk][i] = xb[(k0 + kk) * NN + n0 + i];
        }
        __syncthreads();
        #pragma unroll
        for (int kk = 0; kk < 16; ++kk) {
            float4 a = ((const float4*)Ws[kk])[ty];
            float4 bv = ((const float4*)Xs[kk])[tx];
            acc[0][0] += a.x * bv.x; acc[0][1] += a.x * bv.y; acc[0][2] += a.x * bv.z; acc[0][3] += a.x * bv.w;
            acc[1][0] += a.y * bv.x; acc[1][1] += a.y * bv.y; acc[1][2] += a.y * bv.z; acc[1][3] += a.y * bv.w;
            acc[2][0] += a.z * bv.x; acc[2][1] += a.z * bv.y; acc[2][2] += a.z * bv.z; acc[2][3] += a.z * bv.w;
            acc[3][0] += a.w * bv.x; acc[3][1] += a.w * bv.y; acc[3][2] += a.w * bv.z; acc[3][3] += a.w * bv.w;
        }
        __syncthreads();
    }
    #pragma unroll
    for (int i = 0; i < 4; ++i) {
        int o = o0 + ty * 4 + i;
        float bias = g_Bf[o];
        #pragma unroll
        for (int j = 0; j < 4; ++j) {
            int n = n0 + tx * 4 + j;
            float v = fmaxf(acc[i][j] + bias, 0.0f);
            if (o < 32)       g_Q[((size_t)b * NN + n) * CR + o]          = v;
            else if (o < 64)  g_K[((size_t)b * NN + n) * CR + (o - 32)]   = v;
            else              g_V[((size_t)b * NN + n) * CN + (o - 64)]   = v;
        }
    }
}

// ---------------- flash attention + residual ----------------
// grid (128, 4), 256 threads (8 warps). Each warp owns 4 queries x 256 v-channels,
// each lane: 4 queries x 8 channels (2 float4 chunks). MT=32 queries/block, NT=64 keys/tile.
#define MT 32
#define NT 64
#define FLASH_SMEM ((64*33 + 32*65 + 64*256) * 4)

#define FMA4(A, P, V) { A.x += (P)*(V).x; A.y += (P)*(V).y; A.z += (P)*(V).z; A.w += (P)*(V).w; }
#define MUL4(A, F)    { A.x *= (F); A.y *= (F); A.z *= (F); A.w *= (F); }

__global__ void __launch_bounds__(256, 2)
flash_kernel(const float* __restrict__ x, float* __restrict__ out) {
    extern __shared__ float sm[];
    float* Ks = sm;                 // 64*33
    float* Ss = Ks + 64 * 33;       // 32*65
    float* Vs = Ss + 32 * 65;       // 64*256 (float4-aligned offset)
    float4* Vs4 = (float4*)Vs;

    int b = blockIdx.y;
    int m0 = blockIdx.x * MT;
    int tid = threadIdx.x;
    int lane = tid & 31, warp = tid >> 5;
    int q0 = warp * 4;              // local queries q0..q0+3
    int ql = lane & 3;
    int qq = q0 + ql;               // this lane's score-query

    // cache this lane's query row in registers
    float qreg[32];
    {
        const float4* qsrc = (const float4*)(g_Q + ((size_t)b * NN + m0 + qq) * CR);
        #pragma unroll
        for (int j = 0; j < 8; ++j) {
            float4 v = qsrc[j];
            qreg[4 * j + 0] = v.x; qreg[4 * j + 1] = v.y;
            qreg[4 * j + 2] = v.z; qreg[4 * j + 3] = v.w;
        }
    }

    float m_run[4], l_run[4];
    #pragma unroll
    for (int i = 0; i < 4; ++i) { m_run[i] = -1e30f; l_run[i] = 0.0f; }
    float4 acc[4][2];
    #pragma unroll
    for (int i = 0; i < 4; ++i) { acc[i][0] = make_float4(0,0,0,0); acc[i][1] = make_float4(0,0,0,0); }

    for (int n0 = 0; n0 < NN; n0 += NT) {
        // stage K tile [64][32] (padded 33) and V tile [64][256]
        const float* Ksrc = g_K + ((size_t)b * NN + n0) * CR;
        #pragma unroll
        for (int idx = tid; idx < NT * 32; idx += 256)
            Ks[(idx >> 5) * 33 + (idx & 31)] = Ksrc[idx];
        const float4* Vsrc = (const float4*)(g_V + ((size_t)b * NN + n0) * CN);
        #pragma unroll
        for (int idx = tid; idx < NT * 64; idx += 256)
            Vs4[idx] = Vsrc[idx];
        __syncthreads();

        // scores: lane computes s[q=qq][n = (lane>>2) + 8j]
        float s[8];
        #pragma unroll
        for (int j = 0; j < 8; ++j) {
            int n = (lane >> 2) + 8 * j;
            const float* krow = Ks + n * 33;
            float a = 0.0f;
            #pragma unroll
            for (int c = 0; c < 32; ++c) a += qreg[c] * krow[c];
            s[j] = a;
        }
        // tile max over the 8 lanes sharing this q
        float mloc = s[0];
        #pragma unroll
        for (int j = 1; j < 8; ++j) mloc = fmaxf(mloc, s[j]);
        mloc = fmaxf(mloc, __shfl_xor_sync(0xffffffffu, mloc, 4));
        mloc = fmaxf(mloc, __shfl_xor_sync(0xffffffffu, mloc, 8));
        mloc = fmaxf(mloc, __shfl_xor_sync(0xffffffffu, mloc, 16));

        float m_new_q[4], f_q[4];
        #pragma unroll
        for (int i = 0; i < 4; ++i) {
            float tm = __shfl_sync(0xffffffffu, mloc, i, 4);
            float mn = fmaxf(m_run[i], tm);
            f_q[i] = __expf(m_run[i] - mn);
            m_new_q[i] = mn;
        }
        // p for own scores
        float mnown = m_new_q[ql];
        float lsum = 0.0f;
        #pragma unroll
        for (int j = 0; j < 8; ++j) {
            float p = __expf(s[j] - mnown);
            Ss[qq * 65 + (lane >> 2) + 8 * j] = p;
            lsum += p;
        }
        lsum += __shfl_xor_sync(0xffffffffu, lsum, 4);
        lsum += __shfl_xor_sync(0xffffffffu, lsum, 8);
        lsum += __shfl_xor_sync(0xffffffffu, lsum, 16);
        #pragma unroll
        for (int i = 0; i < 4; ++i) {
            float ls = __shfl_sync(0xffffffffu, lsum, i, 4);
            l_run[i] = l_run[i] * f_q[i] + ls;
            m_run[i] = m_new_q[i];
            float f = f_q[i];
            MUL4(acc[i][0], f);
            MUL4(acc[i][1], f);
        }
        __syncwarp();

        // PV: acc[q][c] += sum_n p[q][n] * V[n][c]
        const float* Srow = Ss + q0 * 65;
        #pragma unroll 2
        for (int n = 0; n < NT; ++n) {
            float4 v0 = Vs4[n * 64 + lane];
            float4 v1 = Vs4[n * 64 + 32 + lane];
            float p0 = Srow[n], p1 = Srow[65 + n], p2 = Srow[130 + n], p3 = Srow[195 + n];
            FMA4(acc[0][0], p0, v0); FMA4(acc[0][1], p0, v1);
            FMA4(acc[1][0], p1, v0); FMA4(acc[1][1], p1, v1);
            FMA4(acc[2][0], p2, v0); FMA4(acc[2][1], p2, v1);
            FMA4(acc[3][0], p3, v0); FMA4(acc[3][1], p3, v1);
        }
        __syncthreads();
    }

    // epilogue: divide by l, transpose through shared (reuse Vs), coalesced x + write
    float* Osh = Vs;    // used as [256][33]: 8448 floats <= 16384
    #pragma unroll
    for (int i = 0; i < 4; ++i) {
        float inv = 1.0f / l_run[i];
        int q = q0 + i;
        float4 a0 = acc[i][0], a1 = acc[i][1];
        int c0 = lane * 4;
        Osh[(c0 + 0) * 33 + q] = a0.x * inv;
        Osh[(c0 + 1) * 33 + q] = a0.y * inv;
        Osh[(c0 + 2) * 33 + q] = a0.z * inv;
        Osh[(c0 + 3) * 33 + q] = a0.w * inv;
        Osh[(128 + c0 + 0) * 33 + q] = a1.x * inv;
        Osh[(128 + c0 + 1) * 33 + q] = a1.y * inv;
        Osh[(128 + c0 + 2) * 33 + q] = a1.z * inv;
        Osh[(128 + c0 + 3) * 33 + q] = a1.w * inv;
    }
    __syncthreads();
    const float* xb = x + (size_t)b * CN * NN;
    float* ob = out + (size_t)b * CN * NN;
    for (int r = warp; r < CN; r += 8) {
        float val = Osh[r * 33 + lane];
        ob[(size_t)r * NN + m0 + lane] = xb[(size_t)r * NN + m0 + lane] + val;
    }
}

// ---------------- launcher ----------------
extern "C" void kernel_launch(void* const* d_in, const int* in_sizes, int n_in,
                              void* d_out, int out_size) {
    const float* x  = (const float*)d_in[0];
    const float* w1 = (const float*)d_in[1];
    const float* w2 = (const float*)d_in[2];
    const float* w3 = (const float*)d_in[3];
    const float* g1 = (const float*)d_in[4];
    const float* b1 = (const float*)d_in[5];
    const float* g2 = (const float*)d_in[6];
    const float* b2 = (const float*)d_in[7];
    const float* g3 = (const float*)d_in[8];
    const float* b3 = (const float*)d_in[9];
    float* out = (float*)d_out;

    cudaFuncSetAttribute(flash_kernel, cudaFuncAttributeMaxDynamicSharedMemorySize, FLASH_SMEM);

    zero_kernel<<<256, 256>>>();
    mean_kernel<<<256, 256>>>(x);
    gram_kernel<<<dim3(8, 8, 16), 256>>>(x);
    fold_kernel<<<320, 256>>>(w1, w2, w3, g1, b1, g2, b2, g3, b3);
    qkd_kernel<<<dim3(5, 64, 4), 256>>>(x);
    flash_kernel<<<dim3(128, 4), 256, FLASH_SMEM>>>(x, out);
}